// round 2
// baseline (speedup 1.0000x reference)
#include <cuda_runtime.h>
#include <math.h>

#define DIM   1024
#define HALF  512
#define NMAX  65536

// ---------------- scratch (device globals; no allocation allowed) ----------------
__device__ float g_qn[DIM];       // l2norm(q_init)
__device__ float g_q[HALF];       // q = qn@Wq + bq
__device__ float g_qk[DIM];       // Wk @ q
__device__ float g_s[NMAX];       // raw scores (pre z-norm)
__device__ float g_invn[NMAX];    // 1/||k_init[n]||
__device__ float g_w[NMAX];       // final per-row weights attn[n]/||row n||
__device__ float g_z[DIM];        // weighted row-sum of k_init
__device__ float g_ctx[DIM];      // z@Wv + bv
__device__ float g_outm[DIM];     // ctx@Wm (bm added at the end)

// ---------------- kernel A: init accumulators + q l2norm (1 block, 1024 thr) ----
__global__ void kern_init(const float* __restrict__ q_init,
                          const float* __restrict__ bq,
                          const float* __restrict__ bv) {
    __shared__ float red[32];
    int t = threadIdx.x;
    float v = q_init[t];
    float ss = v * v;
    #pragma unroll
    for (int o = 16; o; o >>= 1) ss += __shfl_xor_sync(0xFFFFFFFFu, ss, o);
    if ((t & 31) == 0) red[t >> 5] = ss;
    __syncthreads();
    if (t < 32) {
        float x = red[t];
        #pragma unroll
        for (int o = 16; o; o >>= 1) x += __shfl_xor_sync(0xFFFFFFFFu, x, o);
        if (t == 0) red[0] = x;
    }
    __syncthreads();
    float inv = 1.0f / fmaxf(sqrtf(red[0]), 1e-12f);
    g_qn[t]   = v * inv;
    g_z[t]    = 0.0f;
    g_outm[t] = 0.0f;
    g_ctx[t]  = bv[t];
    if (t < HALF) g_q[t] = bq[t];
}

// ---------------- kernel B: q += qn @ Wq  (Wq: [1024,512] row-major) -------------
// grid 64 blocks x 256 thr; block handles 16 d-rows; thread owns cols t and t+256
__global__ void kern_gemv_q(const float* __restrict__ Wq) {
    __shared__ float xs[16];
    int b = blockIdx.x, t = threadIdx.x;
    if (t < 16) xs[t] = g_qn[b * 16 + t];
    __syncthreads();
    const float* W = Wq + (size_t)b * 16 * HALF;
    float a0 = 0.f, a1 = 0.f;
    #pragma unroll
    for (int d = 0; d < 16; d++) {
        float x = xs[d];
        a0 += x * W[d * HALF + t];
        a1 += x * W[d * HALF + t + 256];
    }
    atomicAdd(&g_q[t], a0);
    atomicAdd(&g_q[t + 256], a1);
}

// ---------------- kernel C: qk[d] = Wk[d,:] . q  (Wk: [1024,512]) ----------------
// grid 128 blocks x 256 thr (8 warps); one row per warp
__global__ void kern_gemv_qk(const float* __restrict__ Wk) {
    __shared__ float qs[HALF];
    int t = threadIdx.x;
    qs[t] = g_q[t];
    qs[t + 256] = g_q[t + 256];
    __syncthreads();
    int w = t >> 5, l = t & 31;
    int d = blockIdx.x * 8 + w;
    const float4* row = (const float4*)(Wk + (size_t)d * HALF);
    const float4* q4  = (const float4*)qs;
    float acc = 0.f;
    #pragma unroll
    for (int i = 0; i < 4; i++) {
        float4 v = row[i * 32 + l];
        float4 q = q4[i * 32 + l];
        acc += v.x * q.x + v.y * q.y + v.z * q.z + v.w * q.w;
    }
    #pragma unroll
    for (int o = 16; o; o >>= 1) acc += __shfl_xor_sync(0xFFFFFFFFu, acc, o);
    if (l == 0) g_qk[d] = acc;
}

// ---------------- kernel D: pass 1 over k_init: per-row norm + score -------------
// grid N/8 blocks x 256 thr (8 warps); one row per warp, float4 loads
__global__ void kern_pass1(const float* __restrict__ Kmat) {
    __shared__ float qk_s[DIM];
    int t = threadIdx.x;
    #pragma unroll
    for (int i = 0; i < 4; i++) qk_s[t + i * 256] = g_qk[t + i * 256];
    __syncthreads();
    int w = t >> 5, l = t & 31;
    long n = (long)blockIdx.x * 8 + w;
    const float4* row = (const float4*)(Kmat + n * DIM);
    const float4* q4  = (const float4*)qk_s;
    float ss = 0.f, dp = 0.f;
    #pragma unroll
    for (int i = 0; i < 8; i++) {
        float4 v = row[i * 32 + l];
        float4 q = q4[i * 32 + l];
        ss += v.x * v.x + v.y * v.y + v.z * v.z + v.w * v.w;
        dp += v.x * q.x + v.y * q.y + v.z * q.z + v.w * q.w;
    }
    #pragma unroll
    for (int o = 16; o; o >>= 1) {
        ss += __shfl_xor_sync(0xFFFFFFFFu, ss, o);
        dp += __shfl_xor_sync(0xFFFFFFFFu, dp, o);
    }
    if (l == 0) {
        float inv = 1.0f / fmaxf(sqrtf(ss), 1e-12f);
        g_invn[n] = inv;
        g_s[n] = dp * inv;
    }
}

// ---------------- kernel E: stats + softmax weights (1 block, 1024 thr) ----------
__global__ void kern_softmax(int N) {
    __shared__ double redA[32];
    __shared__ double redB[32];
    __shared__ float  st[2];   // mean, rstd
    __shared__ float  den[1];  // 1/denominator
    int t = threadIdx.x, w = t >> 5, l = t & 31;

    // pass A: sum & sumsq of raw scores
    double s = 0.0, s2 = 0.0;
    for (int i = t; i < N; i += 1024) {
        float v = g_s[i];
        s += v;
        s2 += (double)v * (double)v;
    }
    #pragma unroll
    for (int o = 16; o; o >>= 1) {
        s  += __shfl_xor_sync(0xFFFFFFFFu, s, o);
        s2 += __shfl_xor_sync(0xFFFFFFFFu, s2, o);
    }
    if (l == 0) { redA[w] = s; redB[w] = s2; }
    __syncthreads();
    if (t < 32) {
        double a = redA[t], b = redB[t];
        #pragma unroll
        for (int o = 16; o; o >>= 1) {
            a += __shfl_xor_sync(0xFFFFFFFFu, a, o);
            b += __shfl_xor_sync(0xFFFFFFFFu, b, o);
        }
        if (t == 0) {
            double mean = a / N;
            double var  = (b - (double)N * mean * mean) / (double)(N - 1);
            double sd   = sqrt(var > 0.0 ? var : 0.0);
            st[0] = (float)mean;
            st[1] = (float)(1.0 / (sd + 1e-8));
        }
    }
    __syncthreads();
    float mean = st[0], rstd = st[1];

    // pass B: exp(clip) and denom
    double dsum = 0.0;
    for (int i = t; i < N; i += 1024) {
        float x = (g_s[i] - mean) * rstd;
        x = fminf(fmaxf(x, -10.0f), 10.0f);
        float e = expf(x);
        g_w[i] = e;
        dsum += e;
    }
    #pragma unroll
    for (int o = 16; o; o >>= 1) dsum += __shfl_xor_sync(0xFFFFFFFFu, dsum, o);
    if (l == 0) redA[w] = dsum;
    __syncthreads();
    if (t < 32) {
        double a = redA[t];
        #pragma unroll
        for (int o = 16; o; o >>= 1) a += __shfl_xor_sync(0xFFFFFFFFu, a, o);
        if (t == 0) den[0] = (float)(1.0 / a);
    }
    __syncthreads();
    float invden = den[0];

    // pass C: fold 1/denom and 1/||row|| into the weight
    for (int i = t; i < N; i += 1024)
        g_w[i] = g_w[i] * g_invn[i] * invden;
}

// ---------------- kernel F: pass 2: z[d] = sum_n w[n]*k_init[n,d] ----------------
// grid N/32 blocks x 256 thr; 32 rows per block; thread owns 4 consecutive cols
__global__ void kern_pass2(const float* __restrict__ Kmat) {
    __shared__ float ws[32];
    int t = threadIdx.x;
    long n0 = (long)blockIdx.x * 32;
    if (t < 32) ws[t] = g_w[n0 + t];
    __syncthreads();
    float4 acc = make_float4(0.f, 0.f, 0.f, 0.f);
    const float4* base = (const float4*)Kmat + n0 * (DIM / 4) + t;
    #pragma unroll 8
    for (int r = 0; r < 32; r++) {
        float wv = ws[r];
        float4 v = base[r * (DIM / 4)];
        acc.x += wv * v.x;
        acc.y += wv * v.y;
        acc.z += wv * v.z;
        acc.w += wv * v.w;
    }
    float* zp = &g_z[t * 4];
    atomicAdd(zp + 0, acc.x);
    atomicAdd(zp + 1, acc.y);
    atomicAdd(zp + 2, acc.z);
    atomicAdd(zp + 3, acc.w);
}

// ---------------- kernel G: y += x @ W  (W: [1024,1024] row-major) ---------------
// grid 64 blocks x 256 thr; block owns 16 d-rows; thread owns cols [4t,4t+4)
__global__ void kern_gemv_1024(const float* __restrict__ W,
                               const float* __restrict__ x,
                               float* __restrict__ y) {
    __shared__ float xs[16];
    int b = blockIdx.x, t = threadIdx.x;
    if (t < 16) xs[t] = x[b * 16 + t];
    __syncthreads();
    const float4* W4 = (const float4*)(W + (size_t)b * 16 * DIM) + t;
    float4 acc = make_float4(0.f, 0.f, 0.f, 0.f);
    #pragma unroll
    for (int d = 0; d < 16; d++) {
        float xv = xs[d];
        float4 v = W4[d * (DIM / 4)];
        acc.x += xv * v.x;
        acc.y += xv * v.y;
        acc.z += xv * v.z;
        acc.w += xv * v.w;
    }
    float* yp = y + t * 4;
    atomicAdd(yp + 0, acc.x);
    atomicAdd(yp + 1, acc.y);
    atomicAdd(yp + 2, acc.z);
    atomicAdd(yp + 3, acc.w);
}

// ---------------- kernel H: final gate (1 block, 1024 thr) -----------------------
__global__ void kern_final(const float* __restrict__ q_init,
                           const float* __restrict__ bm,
                           const float* __restrict__ gamma,
                           float* __restrict__ out) {
    int t = threadIdx.x;
    float g = 1.0f / (1.0f + expf(-gamma[0]));
    out[t] = g * q_init[t] + (1.0f - g) * (g_outm[t] + bm[t]);
}

// ---------------- launcher --------------------------------------------------------
extern "C" void kernel_launch(void* const* d_in, const int* in_sizes, int n_in,
                              void* d_out, int out_size) {
    const float* q_init = (const float*)d_in[0];
    const float* k_init = (const float*)d_in[1];
    const float* Wq     = (const float*)d_in[2];
    const float* bq     = (const float*)d_in[3];
    const float* Wk     = (const float*)d_in[4];
    const float* bk     = (const float*)d_in[5];  (void)bk; // cancels under z-norm
    const float* Wv     = (const float*)d_in[6];
    const float* bv     = (const float*)d_in[7];
    const float* Wm     = (const float*)d_in[8];
    const float* bm     = (const float*)d_in[9];
    const float* gamma  = (const float*)d_in[10];
    float* out = (float*)d_out;

    int N = in_sizes[1] / DIM;  // 65536

    float *pz, *pctx, *poutm;
    cudaGetSymbolAddress((void**)&pz,    g_z);
    cudaGetSymbolAddress((void**)&pctx,  g_ctx);
    cudaGetSymbolAddress((void**)&poutm, g_outm);

    kern_init<<<1, 1024>>>(q_init, bq, bv);
    kern_gemv_q<<<64, 256>>>(Wq);
    kern_gemv_qk<<<128, 256>>>(Wk);
    kern_pass1<<<N / 8, 256>>>(k_init);
    kern_softmax<<<1, 1024>>>(N);
    kern_pass2<<<N / 32, 256>>>(k_init);
    kern_gemv_1024<<<64, 256>>>(Wv, pz, pctx);
    kern_gemv_1024<<<64, 256>>>(Wm, pctx, poutm);
    kern_final<<<1, 1024>>>(q_init, bm, gamma, out);
}

// round 3
// speedup vs baseline: 1.9813x; 1.9813x over previous
#include <cuda_runtime.h>
#include <math.h>

#define DIM    1024
#define HALF   512
#define NMAX   65536
#define P2B    512          // pass2 blocks
#define P2ROWS 128          // rows per pass2 block

// ---------------- scratch (device globals) ----------------------------------------
__device__ float  g_qn[DIM];                 // l2norm(q_init)
__device__ float  g_qpart[16 * HALF];        // gemv_q partials
__device__ float  g_qk[DIM];                 // Wk @ q
__device__ float  g_s[NMAX];                 // raw scores
__device__ float  g_invn[NMAX];              // 1/||k_init[n]||
__device__ float  g_w[NMAX];                 // e[n] * invn[n]
__device__ double g_spart[128];              // [0:64) sum, [64:128) sumsq of scores
__device__ float  g_epart[64];               // per-block exp sums
__device__ float  g_zpart[P2B * DIM];        // pass2 partials (2 MB, spread)
__device__ float  g_z[DIM];                  // weighted row-sum
__device__ float  g_vpart[64 * DIM];         // z@Wv partials
__device__ float  g_mpart[64 * DIM];         // ctx@Wm partials

// ---------------- A: init + q l2norm (1 block, 1024 thr) --------------------------
__global__ void kern_init(const float* __restrict__ q_init) {
    __shared__ float red[32];
    int t = threadIdx.x;
    float v = q_init[t];
    float ss = v * v;
    #pragma unroll
    for (int o = 16; o; o >>= 1) ss += __shfl_xor_sync(0xFFFFFFFFu, ss, o);
    if ((t & 31) == 0) red[t >> 5] = ss;
    __syncthreads();
    if (t < 32) {
        float x = red[t];
        #pragma unroll
        for (int o = 16; o; o >>= 1) x += __shfl_xor_sync(0xFFFFFFFFu, x, o);
        if (t == 0) red[0] = x;
    }
    __syncthreads();
    float inv = 1.0f / fmaxf(sqrtf(red[0]), 1e-12f);
    g_qn[t] = v * inv;
    if (t < 128) g_spart[t] = 0.0;
}

// ---------------- B: q partials: 16 blocks x 256 thr, 64 d-rows each --------------
__global__ void kern_gemv_q(const float* __restrict__ Wq) {
    __shared__ float xs[64];
    int b = blockIdx.x, t = threadIdx.x;
    if (t < 64) xs[t] = g_qn[b * 64 + t];
    __syncthreads();
    const float* W = Wq + (size_t)b * 64 * HALF;
    float a0 = 0.f, a1 = 0.f;
    #pragma unroll 16
    for (int d = 0; d < 64; d++) {
        float x = xs[d];
        a0 += x * W[d * HALF + t];
        a1 += x * W[d * HALF + t + 256];
    }
    g_qpart[b * HALF + t]       = a0;
    g_qpart[b * HALF + t + 256] = a1;
}

// ---------------- C: qk[d] = Wk[d,:] . q ; combines q partials ---------------------
// 128 blocks x 256 thr (8 warps); one row per warp
__global__ void kern_gemv_qk(const float* __restrict__ Wk,
                             const float* __restrict__ bq) {
    __shared__ float qs[HALF];
    int t = threadIdx.x;
    #pragma unroll
    for (int j = 0; j < 2; j++) {
        int c = t + j * 256;
        float acc = bq[c];
        #pragma unroll
        for (int p = 0; p < 16; p++) acc += g_qpart[p * HALF + c];
        qs[c] = acc;
    }
    __syncthreads();
    int w = t >> 5, l = t & 31;
    int d = blockIdx.x * 8 + w;
    const float4* row = (const float4*)(Wk + (size_t)d * HALF);
    const float4* q4  = (const float4*)qs;
    float acc = 0.f;
    #pragma unroll
    for (int i = 0; i < 4; i++) {
        float4 v = row[i * 32 + l];
        float4 q = q4[i * 32 + l];
        acc += v.x * q.x + v.y * q.y + v.z * q.z + v.w * q.w;
    }
    #pragma unroll
    for (int o = 16; o; o >>= 1) acc += __shfl_xor_sync(0xFFFFFFFFu, acc, o);
    if (l == 0) g_qk[d] = acc;
}

// ---------------- D: pass 1: per-row norm + score + stat partials ------------------
// N/8 blocks x 256 thr (8 warps); one row per warp
__global__ void kern_pass1(const float* __restrict__ Kmat) {
    __shared__ float qk_s[DIM];
    __shared__ float sc[8];
    int t = threadIdx.x;
    #pragma unroll
    for (int i = 0; i < 4; i++) qk_s[t + i * 256] = g_qk[t + i * 256];
    __syncthreads();
    int w = t >> 5, l = t & 31;
    long n = (long)blockIdx.x * 8 + w;
    const float4* row = (const float4*)(Kmat + n * DIM);
    const float4* q4  = (const float4*)qk_s;
    float ss = 0.f, dp = 0.f;
    #pragma unroll
    for (int i = 0; i < 8; i++) {
        float4 v = row[i * 32 + l];
        float4 q = q4[i * 32 + l];
        ss += v.x * v.x + v.y * v.y + v.z * v.z + v.w * v.w;
        dp += v.x * q.x + v.y * q.y + v.z * q.z + v.w * q.w;
    }
    #pragma unroll
    for (int o = 16; o; o >>= 1) {
        ss += __shfl_xor_sync(0xFFFFFFFFu, ss, o);
        dp += __shfl_xor_sync(0xFFFFFFFFu, dp, o);
    }
    if (l == 0) {
        float inv = 1.0f / fmaxf(sqrtf(ss), 1e-12f);
        float s = dp * inv;
        g_invn[n] = inv;
        g_s[n] = s;
        sc[w] = s;
    }
    __syncthreads();
    if (t == 0) {
        double a = 0.0, b2 = 0.0;
        #pragma unroll
        for (int i = 0; i < 8; i++) {
            double x = (double)sc[i];
            a += x; b2 += x * x;
        }
        int slot = blockIdx.x & 63;
        atomicAdd(&g_spart[slot], a);
        atomicAdd(&g_spart[64 + slot], b2);
    }
}

// ---------------- E: exp kernel: 64 blocks x 256 thr -------------------------------
// finalizes stats, w[i] = exp(clip(z-score))*invn[i], per-block e-sum
__global__ void kern_exp(int N) {
    __shared__ float st[2];     // mean, rstd
    __shared__ float red[8];
    int t = threadIdx.x, w = t >> 5, l = t & 31;
    if (w == 0) {
        double a = g_spart[l] + g_spart[l + 32];
        double b = g_spart[64 + l] + g_spart[96 + l];
        #pragma unroll
        for (int o = 16; o; o >>= 1) {
            a += __shfl_xor_sync(0xFFFFFFFFu, a, o);
            b += __shfl_xor_sync(0xFFFFFFFFu, b, o);
        }
        if (l == 0) {
            double mean = a / N;
            double var  = (b - (double)N * mean * mean) / (double)(N - 1);
            double sd   = sqrt(var > 0.0 ? var : 0.0);
            st[0] = (float)mean;
            st[1] = (float)(1.0 / (sd + 1e-8));
        }
    }
    __syncthreads();
    float mean = st[0], rstd = st[1];

    int idx4 = blockIdx.x * 256 + t;
    float4 s4 = ((const float4*)g_s)[idx4];
    float4 in4 = ((const float4*)g_invn)[idx4];
    float4 e4, w4;
    e4.x = expf(fminf(fmaxf((s4.x - mean) * rstd, -10.f), 10.f));
    e4.y = expf(fminf(fmaxf((s4.y - mean) * rstd, -10.f), 10.f));
    e4.z = expf(fminf(fmaxf((s4.z - mean) * rstd, -10.f), 10.f));
    e4.w = expf(fminf(fmaxf((s4.w - mean) * rstd, -10.f), 10.f));
    w4.x = e4.x * in4.x; w4.y = e4.y * in4.y;
    w4.z = e4.z * in4.z; w4.w = e4.w * in4.w;
    ((float4*)g_w)[idx4] = w4;

    float es = e4.x + e4.y + e4.z + e4.w;
    #pragma unroll
    for (int o = 16; o; o >>= 1) es += __shfl_xor_sync(0xFFFFFFFFu, es, o);
    if (l == 0) red[w] = es;
    __syncthreads();
    if (t == 0) {
        float tot = 0.f;
        #pragma unroll
        for (int i = 0; i < 8; i++) tot += red[i];
        g_epart[blockIdx.x] = tot;
    }
}

// ---------------- F: pass 2: partial weighted row-sums, NO atomics -----------------
// P2B blocks x 256 thr; each block 128 rows; thread owns float4 column t
__global__ void kern_pass2(const float* __restrict__ Kmat) {
    __shared__ float ws[P2ROWS];
    __shared__ float invden_s;
    int t = threadIdx.x, w = t >> 5, l = t & 31;
    long n0 = (long)blockIdx.x * P2ROWS;

    if (w == 0) {
        float d = g_epart[l] + g_epart[l + 32];
        #pragma unroll
        for (int o = 16; o; o >>= 1) d += __shfl_xor_sync(0xFFFFFFFFu, d, o);
        if (l == 0) invden_s = 1.0f / d;
    }
    __syncthreads();
    float invden = invden_s;
    if (t < P2ROWS) ws[t] = g_w[n0 + t] * invden;
    __syncthreads();

    float4 acc = make_float4(0.f, 0.f, 0.f, 0.f);
    const float4* base = (const float4*)Kmat + n0 * (DIM / 4) + t;
    #pragma unroll 8
    for (int r = 0; r < P2ROWS; r++) {
        float wv = ws[r];
        float4 v = base[(long)r * (DIM / 4)];
        acc.x += wv * v.x;
        acc.y += wv * v.y;
        acc.z += wv * v.z;
        acc.w += wv * v.w;
    }
    ((float4*)g_zpart)[blockIdx.x * (DIM / 4) + t] = acc;
}

// ---------------- G: reduce z partials: 4 blocks x 256 thr -------------------------
__global__ void kern_zred() {
    int col4 = blockIdx.x * 256 + threadIdx.x;   // 0..1023 float4 cols? no: DIM/4=256
    // grid 1 block would suffice; use 1 block x 256 (each thread one float4 col)
    float4 acc = make_float4(0.f, 0.f, 0.f, 0.f);
    const float4* zp = (const float4*)g_zpart + col4;
    #pragma unroll 8
    for (int b = 0; b < P2B; b++) {
        float4 v = zp[b * (DIM / 4)];
        acc.x += v.x; acc.y += v.y; acc.z += v.z; acc.w += v.w;
    }
    ((float4*)g_z)[col4] = acc;
}

// ---------------- H: z@Wv partials: 64 blocks x 256 thr ----------------------------
__global__ void kern_gemv_v(const float* __restrict__ Wv) {
    __shared__ float xs[16];
    int b = blockIdx.x, t = threadIdx.x;
    if (t < 16) xs[t] = g_z[b * 16 + t];
    __syncthreads();
    const float4* W4 = (const float4*)(Wv + (size_t)b * 16 * DIM) + t;
    float4 acc = make_float4(0.f, 0.f, 0.f, 0.f);
    #pragma unroll
    for (int d = 0; d < 16; d++) {
        float xv = xs[d];
        float4 v = W4[d * (DIM / 4)];
        acc.x += xv * v.x;
        acc.y += xv * v.y;
        acc.z += xv * v.z;
        acc.w += xv * v.w;
    }
    ((float4*)g_vpart)[b * (DIM / 4) + t] = acc;
}

// ---------------- I: ctx@Wm partials; combines v partials for its slice ------------
// 64 blocks x 256 thr
__global__ void kern_gemv_m(const float* __restrict__ Wm,
                            const float* __restrict__ bv) {
    __shared__ float part[16][17];
    __shared__ float xs[16];
    int b = blockIdx.x, t = threadIdx.x;
    // ctx[b*16 + (t&15)] partial over 4 of the 64 v-partials per thread
    {
        int c = b * 16 + (t & 15);
        int pg = t >> 4;                 // 0..15
        float a = 0.f;
        #pragma unroll
        for (int j = 0; j < 4; j++) a += g_vpart[(pg * 4 + j) * DIM + c];
        part[t & 15][pg] = a;
    }
    __syncthreads();
    if (t < 16) {
        float a = bv[b * 16 + t];
        #pragma unroll
        for (int i = 0; i < 16; i++) a += part[t][i];
        xs[t] = a;
    }
    __syncthreads();
    const float4* W4 = (const float4*)(Wm + (size_t)b * 16 * DIM) + t;
    float4 acc = make_float4(0.f, 0.f, 0.f, 0.f);
    #pragma unroll
    for (int d = 0; d < 16; d++) {
        float xv = xs[d];
        float4 v = W4[d * (DIM / 4)];
        acc.x += xv * v.x;
        acc.y += xv * v.y;
        acc.z += xv * v.z;
        acc.w += xv * v.w;
    }
    ((float4*)g_mpart)[b * (DIM / 4) + t] = acc;
}

// ---------------- J: final gate (1 block, 1024 thr) --------------------------------
__global__ void kern_final(const float* __restrict__ q_init,
                           const float* __restrict__ bm,
                           const float* __restrict__ gamma,
                           float* __restrict__ out) {
    int t = threadIdx.x;
    float acc = bm[t];
    #pragma unroll 8
    for (int p = 0; p < 64; p++) acc += g_mpart[p * DIM + t];
    float g = 1.0f / (1.0f + expf(-gamma[0]));
    out[t] = g * q_init[t] + (1.0f - g) * acc;
}

// ---------------- launcher ----------------------------------------------------------
extern "C" void kernel_launch(void* const* d_in, const int* in_sizes, int n_in,
                              void* d_out, int out_size) {
    const float* q_init = (const float*)d_in[0];
    const float* k_init = (const float*)d_in[1];
    const float* Wq     = (const float*)d_in[2];
    const float* bq     = (const float*)d_in[3];
    const float* Wk     = (const float*)d_in[4];
    // d_in[5] = bk: cancels under z-score normalization of scores
    const float* Wv     = (const float*)d_in[6];
    const float* bv     = (const float*)d_in[7];
    const float* Wm     = (const float*)d_in[8];
    const float* bm     = (const float*)d_in[9];
    const float* gamma  = (const float*)d_in[10];
    float* out = (float*)d_out;

    int N = in_sizes[1] / DIM;  // 65536

    kern_init<<<1, 1024>>>(q_init);
    kern_gemv_q<<<16, 256>>>(Wq);
    kern_gemv_qk<<<128, 256>>>(Wk, bq);
    kern_pass1<<<N / 8, 256>>>(k_init);
    kern_exp<<<64, 256>>>(N);
    kern_pass2<<<P2B, 256>>>(k_init);
    kern_zred<<<1, 256>>>();
    kern_gemv_v<<<64, 256>>>(Wv);
    kern_gemv_m<<<64, 256>>>(Wm, bv);
    kern_final<<<1, 1024>>>(q_init, bm, gamma, out);
}

// round 4
// speedup vs baseline: 2.8669x; 1.4470x over previous
#include <cuda_runtime.h>
#include <math.h>

#define DIM    1024
#define HALF   512
#define NMAX   65536
#define P2B    512          // pass2 blocks
#define P2ROWS 128          // rows per pass2 block

// ---------------- scratch (device globals) ----------------------------------------
__device__ float    g_qpart[64 * HALF];      // Wq GEMV partials
__device__ float    g_qk[DIM];               // Wk @ q
__device__ float    g_s[NMAX];               // raw scores
__device__ float    g_invn[NMAX];            // 1/||k_init[n]||
__device__ double   g_spart[128];            // [0:64) sum, [64:128) sumsq
__device__ float    g_epart[P2B];            // per-pass2-block exp sums
__device__ float    g_zpart[P2B * DIM];      // pass2 partial row-sums
__device__ float    g_vpart[64 * DIM];       // z@Wv partials
__device__ float    g_mpart[64 * DIM];       // ctx@Wm partials
__device__ unsigned g_sync = 0;              // generation-based grid barrier

// ---------------- grid barrier (all blocks must be resident!) ----------------------
__device__ __forceinline__ void grid_sync(unsigned nb) {
    __syncthreads();
    if (threadIdx.x == 0) {
        __threadfence();
        unsigned gen = atomicAdd(&g_sync, 1u);
        unsigned target = (gen / nb + 1u) * nb;
        while (atomicAdd(&g_sync, 0u) < target) __nanosleep(64);
        __threadfence();
    }
    __syncthreads();
}

// ---------------- kernel 1: q-norm + Wq GEMV + Wk GEMV (64 blocks x 256 thr) ------
__global__ void kern_pre(const float* __restrict__ q_init,
                         const float* __restrict__ Wq,
                         const float* __restrict__ Wk,
                         const float* __restrict__ bq) {
    __shared__ float qn_s[DIM];
    __shared__ float qs[HALF];
    __shared__ float red[8];
    int b = blockIdx.x, t = threadIdx.x, w = t >> 5, l = t & 31;

    if (b == 0 && t < 128) g_spart[t] = 0.0;   // reset stats each replay

    // redundant q l2norm per block (4 KB read, L2 hit)
    float4 v = ((const float4*)q_init)[t];
    float ss = v.x * v.x + v.y * v.y + v.z * v.z + v.w * v.w;
    #pragma unroll
    for (int o = 16; o; o >>= 1) ss += __shfl_xor_sync(0xFFFFFFFFu, ss, o);
    if (l == 0) red[w] = ss;
    __syncthreads();
    if (t == 0) {
        float tot = 0.f;
        #pragma unroll
        for (int i = 0; i < 8; i++) tot += red[i];
        red[0] = 1.0f / fmaxf(sqrtf(tot), 1e-12f);
    }
    __syncthreads();
    float inv = red[0];
    ((float4*)qn_s)[t] = make_float4(v.x * inv, v.y * inv, v.z * inv, v.w * inv);
    __syncthreads();

    // Wq GEMV partial: block b owns d-rows [b*16, b*16+16)
    {
        const float* W = Wq + (size_t)b * 16 * HALF;
        float a0 = 0.f, a1 = 0.f;
        #pragma unroll
        for (int d = 0; d < 16; d++) {
            float x = qn_s[b * 16 + d];
            a0 += x * W[d * HALF + t];
            a1 += x * W[d * HALF + t + 256];
        }
        g_qpart[b * HALF + t]       = a0;
        g_qpart[b * HALF + t + 256] = a1;
    }

    grid_sync(64);

    // combine q = bq + sum(partials)
    #pragma unroll
    for (int j = 0; j < 2; j++) {
        int c = t + j * 256;
        float acc = bq[c];
        #pragma unroll 16
        for (int p = 0; p < 64; p++) acc += g_qpart[p * HALF + c];
        qs[c] = acc;
    }
    __syncthreads();

    // Wk GEMV: block b owns qk rows [b*16, b*16+16); 8 warps x 2 rows
    #pragma unroll
    for (int r = 0; r < 2; r++) {
        int d = b * 16 + w * 2 + r;
        const float4* row = (const float4*)(Wk + (size_t)d * HALF);
        const float4* q4  = (const float4*)qs;
        float acc = 0.f;
        #pragma unroll
        for (int i = 0; i < 4; i++) {
            float4 vv = row[i * 32 + l];
            float4 qq = q4[i * 32 + l];
            acc += vv.x * qq.x + vv.y * qq.y + vv.z * qq.z + vv.w * qq.w;
        }
        #pragma unroll
        for (int o = 16; o; o >>= 1) acc += __shfl_xor_sync(0xFFFFFFFFu, acc, o);
        if (l == 0) g_qk[d] = acc;
    }
}

// ---------------- kernel 2: pass 1 over k_init (N/8 blocks x 256 thr) --------------
__global__ void kern_pass1(const float* __restrict__ Kmat) {
    __shared__ float qk_s[DIM];
    __shared__ float sc[8];
    int t = threadIdx.x;
    #pragma unroll
    for (int i = 0; i < 4; i++) qk_s[t + i * 256] = g_qk[t + i * 256];
    __syncthreads();
    int w = t >> 5, l = t & 31;
    long n = (long)blockIdx.x * 8 + w;
    const float4* row = (const float4*)(Kmat + n * DIM);
    const float4* q4  = (const float4*)qk_s;
    float ss = 0.f, dp = 0.f;
    #pragma unroll
    for (int i = 0; i < 8; i++) {
        float4 v = __ldcs(row + i * 32 + l);
        float4 q = q4[i * 32 + l];
        ss += v.x * v.x + v.y * v.y + v.z * v.z + v.w * v.w;
        dp += v.x * q.x + v.y * q.y + v.z * q.z + v.w * q.w;
    }
    #pragma unroll
    for (int o = 16; o; o >>= 1) {
        ss += __shfl_xor_sync(0xFFFFFFFFu, ss, o);
        dp += __shfl_xor_sync(0xFFFFFFFFu, dp, o);
    }
    if (l == 0) {
        float inv = 1.0f / fmaxf(sqrtf(ss), 1e-12f);
        float s = dp * inv;
        g_invn[n] = inv;
        g_s[n] = s;
        sc[w] = s;
    }
    __syncthreads();
    if (t == 0) {
        double a = 0.0, b2 = 0.0;
        #pragma unroll
        for (int i = 0; i < 8; i++) {
            double x = (double)sc[i];
            a += x; b2 += x * x;
        }
        int slot = blockIdx.x & 63;
        atomicAdd(&g_spart[slot], a);
        atomicAdd(&g_spart[64 + slot], b2);
    }
}

// ---------------- kernel 3: pass 2 with fused exp (P2B blocks x 256 thr) -----------
__global__ void kern_pass2(const float* __restrict__ Kmat, int N) {
    __shared__ float ws[P2ROWS];
    __shared__ float st[2];    // mean, rstd
    __shared__ float red[8];
    int t = threadIdx.x, w = t >> 5, l = t & 31;
    long n0 = (long)blockIdx.x * P2ROWS;

    // finalize stats (redundant per block; 128 doubles, L2 hit)
    if (t < 32) {
        double a  = g_spart[t]      + g_spart[t + 32];
        double b2 = g_spart[64 + t] + g_spart[96 + t];
        #pragma unroll
        for (int o = 16; o; o >>= 1) {
            a  += __shfl_xor_sync(0xFFFFFFFFu, a, o);
            b2 += __shfl_xor_sync(0xFFFFFFFFu, b2, o);
        }
        if (t == 0) {
            double mean = a / N;
            double var  = (b2 - (double)N * mean * mean) / (double)(N - 1);
            double sd   = sqrt(var > 0.0 ? var : 0.0);
            st[0] = (float)mean;
            st[1] = (float)(1.0 / (sd + 1e-8));
        }
    }
    __syncthreads();
    float mean = st[0], rstd = st[1];

    // this block's 128 weights: w = exp(clip(zscore)) * invn ; e-sum to g_epart
    float e = 0.f;
    if (t < P2ROWS) {
        float s   = g_s[n0 + t];
        float inv = g_invn[n0 + t];
        float x = fminf(fmaxf((s - mean) * rstd, -10.f), 10.f);
        e = expf(x);
        ws[t] = e * inv;
    }
    #pragma unroll
    for (int o = 16; o; o >>= 1) e += __shfl_xor_sync(0xFFFFFFFFu, e, o);
    if (l == 0) red[w] = e;
    __syncthreads();
    if (t == 0) {
        float tot = 0.f;
        #pragma unroll
        for (int i = 0; i < 4; i++) tot += red[i];   // warps 4..7 hold zeros
        g_epart[blockIdx.x] = tot;
    }
    __syncthreads();

    // weighted row-sum partials (1/denom deferred to kern_post)
    float4 acc = make_float4(0.f, 0.f, 0.f, 0.f);
    const float4* base = (const float4*)Kmat + n0 * (DIM / 4) + t;
    #pragma unroll 8
    for (int r = 0; r < P2ROWS; r++) {
        float wv = ws[r];
        float4 v = __ldcs(base + (long)r * (DIM / 4));
        acc.x += wv * v.x;
        acc.y += wv * v.y;
        acc.z += wv * v.z;
        acc.w += wv * v.w;
    }
    ((float4*)g_zpart)[blockIdx.x * (DIM / 4) + t] = acc;
}

// ---------------- kernel 4: z-reduce + Wv GEMV + Wm GEMV + gate (64 x 256) ---------
__global__ void kern_post(const float* __restrict__ Wv,
                          const float* __restrict__ Wm,
                          const float* __restrict__ bv,
                          const float* __restrict__ bm,
                          const float* __restrict__ q_init,
                          const float* __restrict__ gamma,
                          float* __restrict__ out) {
    __shared__ float cred[16][17];
    __shared__ float xs[16];
    __shared__ float red[8];
    __shared__ float invden_s;
    int b = blockIdx.x, t = threadIdx.x, w = t >> 5, l = t & 31;
    int j = t & 15, g = t >> 4;   // 16 cols x 16 groups

    // denom = sum of 512 e-partials (redundant per block)
    {
        float d = g_epart[t] + g_epart[t + 256];
        #pragma unroll
        for (int o = 16; o; o >>= 1) d += __shfl_xor_sync(0xFFFFFFFFu, d, o);
        if (l == 0) red[w] = d;
        __syncthreads();
        if (t == 0) {
            float tot = 0.f;
            #pragma unroll
            for (int i = 0; i < 8; i++) tot += red[i];
            invden_s = 1.0f / tot;
        }
        __syncthreads();
    }
    float invden = invden_s;

    // z slice for cols [b*16, b*16+16): reduce 512 zparts
    {
        float a = 0.f;
        #pragma unroll 8
        for (int k = 0; k < 32; k++)
            a += g_zpart[(g * 32 + k) * DIM + b * 16 + j];
        cred[j][g] = a;
        __syncthreads();
        if (t < 16) {
            float s = 0.f;
            #pragma unroll
            for (int i = 0; i < 16; i++) s += cred[t][i];
            xs[t] = s * invden;
        }
        __syncthreads();
    }

    // Wv GEMV partial from z slice
    {
        const float4* W4 = (const float4*)(Wv + (size_t)b * 16 * DIM) + t;
        float4 acc = make_float4(0.f, 0.f, 0.f, 0.f);
        #pragma unroll
        for (int d = 0; d < 16; d++) {
            float xv = xs[d];
            float4 v = W4[d * (DIM / 4)];
            acc.x += xv * v.x;
            acc.y += xv * v.y;
            acc.z += xv * v.z;
            acc.w += xv * v.w;
        }
        ((float4*)g_vpart)[b * (DIM / 4) + t] = acc;
    }

    grid_sync(64);

    // ctx slice: bv + reduce of 64 v-partials over cols [b*16, b*16+16)
    {
        float a = 0.f;
        #pragma unroll
        for (int k = 0; k < 4; k++)
            a += g_vpart[(g * 4 + k) * DIM + b * 16 + j];
        cred[j][g] = a;
        __syncthreads();
        if (t < 16) {
            float s = bv[b * 16 + t];
            #pragma unroll
            for (int i = 0; i < 16; i++) s += cred[t][i];
            xs[t] = s;
        }
        __syncthreads();
    }

    // Wm GEMV partial from ctx slice
    {
        const float4* W4 = (const float4*)(Wm + (size_t)b * 16 * DIM) + t;
        float4 acc = make_float4(0.f, 0.f, 0.f, 0.f);
        #pragma unroll
        for (int d = 0; d < 16; d++) {
            float xv = xs[d];
            float4 v = W4[d * (DIM / 4)];
            acc.x += xv * v.x;
            acc.y += xv * v.y;
            acc.z += xv * v.z;
            acc.w += xv * v.w;
        }
        ((float4*)g_mpart)[b * (DIM / 4) + t] = acc;
    }

    grid_sync(64);

    // final gate for out cols [b*16, b*16+16)
    {
        float a = 0.f;
        #pragma unroll
        for (int k = 0; k < 4; k++)
            a += g_mpart[(g * 4 + k) * DIM + b * 16 + j];
        cred[j][g] = a;
        __syncthreads();
        if (t < 16) {
            int c = b * 16 + t;
            float s = bm[c];
            #pragma unroll
            for (int i = 0; i < 16; i++) s += cred[t][i];
            float gg = 1.0f / (1.0f + expf(-gamma[0]));
            out[c] = gg * q_init[c] + (1.0f - gg) * s;
        }
    }
}

// ---------------- launcher ----------------------------------------------------------
extern "C" void kernel_launch(void* const* d_in, const int* in_sizes, int n_in,
                              void* d_out, int out_size) {
    const float* q_init = (const float*)d_in[0];
    const float* k_init = (const float*)d_in[1];
    const float* Wq     = (const float*)d_in[2];
    const float* bq     = (const float*)d_in[3];
    const float* Wk     = (const float*)d_in[4];
    // d_in[5] = bk: cancels under z-score normalization of scores
    const float* Wv     = (const float*)d_in[6];
    const float* bv     = (const float*)d_in[7];
    const float* Wm     = (const float*)d_in[8];
    const float* bm     = (const float*)d_in[9];
    const float* gamma  = (const float*)d_in[10];
    float* out = (float*)d_out;

    int N = in_sizes[1] / DIM;  // 65536

    kern_pre  <<<64, 256>>>(q_init, Wq, Wk, bq);
    kern_pass1<<<N / 8, 256>>>(k_init);
    kern_pass2<<<P2B, 256>>>(k_init, N);
    kern_post <<<64, 256>>>(Wv, Wm, bv, bm, q_init, gamma, out);
}